// round 3
// baseline (speedup 1.0000x reference)
#include <cuda_runtime.h>
#include <math_constants.h>

// Problem constants
#define BB    4
#define NN    1024      // src points per batch
#define MM    65536     // H*W target points per batch
#define CC    64        // desc channels
#define VCH   72        // padded V row stride (0..63 raw desc, 64..66 coords, 67 weight)
#define SCALE 1.5625f   // 1/(C*TEMP) = 1/(64*0.01)

#define TQ 64
#define TK 64
#define LDC 68          // padded smem row stride (floats), 272B = 16B aligned, conflict-free
#define KSPLIT 16
#define NBLK (BB*16*KSPLIT)   // 4 * (1024/64) * 16 = 1024 partial blocks

// Scratch (static __device__ arrays: allocation-free per harness rules)
__device__ float g_Q[BB*NN*CC];                       //  1 MB  [b][n][c]
__device__ float g_K[(size_t)BB*MM*CC];               // 64 MB  [b][m][c]
__device__ float g_V[(size_t)BB*MM*VCH];              // 75 MB  [b][m][cv]
__device__ float g_part[(size_t)NBLK*64*68];          // 18 MB  [blk][cv][q]
__device__ float g_pm[NBLK*64];
__device__ float g_pl[NBLK*64];

// ---------------------------------------------------------------------------
// Normalize src_desc -> Q  (zn over channel dim, ddof=1)
// ---------------------------------------------------------------------------
__global__ void norm_src_kernel(const float* __restrict__ src_desc) {
    int gid = blockIdx.x * blockDim.x + threadIdx.x;   // 4096 = B*N
    int b = gid >> 10, n = gid & 1023;
    const float* p = src_desc + (size_t)b * CC * NN + n;
    float xs[CC];
    float sum = 0.f;
#pragma unroll
    for (int c = 0; c < CC; c++) { xs[c] = p[c * NN]; sum += xs[c]; }
    float mean = sum * (1.f / 64.f);
    float var = 0.f;
#pragma unroll
    for (int c = 0; c < CC; c++) { float d = xs[c] - mean; var += d * d; }
    float inv = rsqrtf(var * (1.f / 63.f));
    float* q = g_Q + (size_t)gid * CC;
#pragma unroll
    for (int c = 0; c < CC; c++) q[c] = (xs[c] - mean) * inv;
}

// ---------------------------------------------------------------------------
// Normalize tgt_desc -> K ; pack V = [raw desc | coords | weight]
// ---------------------------------------------------------------------------
__global__ void norm_tgt_kernel(const float* __restrict__ tgt_desc,
                                const float* __restrict__ tgt_coords,
                                const float* __restrict__ tgt_w) {
    int gid = blockIdx.x * blockDim.x + threadIdx.x;   // 262144 = B*M
    int b = gid >> 16, m = gid & 65535;
    const float* p = tgt_desc + (size_t)b * CC * MM + m;
    float xs[CC];
    float sum = 0.f;
#pragma unroll
    for (int c = 0; c < CC; c++) { xs[c] = p[(size_t)c * MM]; sum += xs[c]; }
    float mean = sum * (1.f / 64.f);
    float var = 0.f;
#pragma unroll
    for (int c = 0; c < CC; c++) { float d = xs[c] - mean; var += d * d; }
    float inv = rsqrtf(var * (1.f / 63.f));
    float* kk = g_K + (size_t)gid * CC;
    float* vv = g_V + (size_t)gid * VCH;
#pragma unroll
    for (int c = 0; c < CC; c++) { kk[c] = (xs[c] - mean) * inv; vv[c] = xs[c]; }
    vv[64] = tgt_coords[(size_t)(b * 3 + 0) * MM + m];
    vv[65] = tgt_coords[(size_t)(b * 3 + 1) * MM + m];
    vv[66] = tgt_coords[(size_t)(b * 3 + 2) * MM + m];
    vv[67] = tgt_w[(size_t)b * MM + m];
}

// ---------------------------------------------------------------------------
// Fused flash attention, fp32, 4x4 register tiles, split-KV partials
// grid: (KSPLIT, N/TQ, B), block: 256
// ---------------------------------------------------------------------------
__global__ __launch_bounds__(256, 2) void attn_kernel() {
    extern __shared__ float sm[];
    float* Qs  = sm;                 // [64][LDC]  (q, c)
    float* Ks  = Qs  + TQ * LDC;     // [64][LDC]  (k, c)
    float* Ps  = Ks  + TK * LDC;     // [64][LDC]  (q, k)
    float* VsT = Ps  + TQ * LDC;     // [68][LDC]  (cv, k)
    float* mS  = VsT + 68 * LDC;     // [64]
    float* lS  = mS + 64;            // [64]
    float* cS  = lS + 64;            // [64]

    const int ks = blockIdx.x;       // key split 0..15
    const int qt = blockIdx.y;       // q tile 0..15
    const int b  = blockIdx.z;
    const int tid = threadIdx.x;
    const int ty = tid >> 4, tx = tid & 15;

    // Load Q tile (coalesced)
    const float* Qg = g_Q + ((size_t)b * NN + qt * TQ) * CC;
    for (int i = tid; i < TQ * CC; i += 256) {
        int q = i >> 6, c = i & 63;
        Qs[q * LDC + c] = Qg[q * CC + c];
    }
    if (tid < 64) { mS[tid] = -CUDART_INF_F; lS[tid] = 0.f; }

    float Oa[4][4];
#pragma unroll
    for (int i = 0; i < 4; i++)
#pragma unroll
        for (int j = 0; j < 4; j++) Oa[i][j] = 0.f;
    float Ob = 0.f;
    const int obq = tid >> 2;            // phase-2b query
    const int obc = 64 + (tid & 3);      // phase-2b channel (coords/weight)

    const int kbase = ks * (MM / KSPLIT);
    const float* Kg = g_K + ((size_t)b * MM + kbase) * CC;
    const float* Vg = g_V + ((size_t)b * MM + kbase) * VCH;

    __syncthreads();

    for (int kt = 0; kt < (MM / KSPLIT) / TK; kt++) {
        // ---- load K tile and V tile (V transposed to [cv][k]) ----
        const float* Kt = Kg + (size_t)(kt * TK) * CC;
        for (int i = tid; i < TK * CC; i += 256) {
            int k = i >> 6, c = i & 63;
            Ks[k * LDC + c] = Kt[k * CC + c];
        }
        const float* Vt = Vg + (size_t)(kt * TK) * VCH;
        for (int i = tid; i < TK * 68; i += 256) {
            int k = i / 68, cv = i - k * 68;
            VsT[cv * LDC + k] = Vt[k * VCH + cv];
        }
        __syncthreads();

        // ---- phase 1: S = Q K^T (4x4 per thread) ----
        float acc[4][4];
#pragma unroll
        for (int i = 0; i < 4; i++)
#pragma unroll
            for (int j = 0; j < 4; j++) acc[i][j] = 0.f;

        const float* qrow = Qs + (ty * 4) * LDC;
        const float* krow = Ks + (tx * 4) * LDC;
#pragma unroll
        for (int c4 = 0; c4 < CC; c4 += 4) {
            float4 av[4], bv[4];
#pragma unroll
            for (int i = 0; i < 4; i++) av[i] = *(const float4*)(qrow + i * LDC + c4);
#pragma unroll
            for (int j = 0; j < 4; j++) bv[j] = *(const float4*)(krow + j * LDC + c4);
#pragma unroll
            for (int i = 0; i < 4; i++)
#pragma unroll
                for (int j = 0; j < 4; j++)
                    acc[i][j] += av[i].x * bv[j].x + av[i].y * bv[j].y
                               + av[i].z * bv[j].z + av[i].w * bv[j].w;
        }

        // ---- online softmax bookkeeping (row groups owned by half-warps) ----
#pragma unroll
        for (int i = 0; i < 4; i++) {
            float rm = fmaxf(fmaxf(acc[i][0], acc[i][1]), fmaxf(acc[i][2], acc[i][3]));
#pragma unroll
            for (int off = 8; off > 0; off >>= 1)
                rm = fmaxf(rm, __shfl_xor_sync(0xffffffffu, rm, off));
            int q = ty * 4 + i;
            float mo = mS[q];
            float mn = fmaxf(mo, rm);
            float corr = __expf(SCALE * (mo - mn));   // -inf -> 0 on first tile
            float rs = 0.f;
#pragma unroll
            for (int j = 0; j < 4; j++) {
                float p = __expf(SCALE * (acc[i][j] - mn));
                Ps[q * LDC + tx * 4 + j] = p;
                rs += p;
            }
#pragma unroll
            for (int off = 8; off > 0; off >>= 1)
                rs += __shfl_xor_sync(0xffffffffu, rs, off);
            if (tx == 0) { mS[q] = mn; lS[q] = lS[q] * corr + rs; cS[q] = corr; }
        }
        __syncthreads();

        // ---- rescale accumulators ----
#pragma unroll
        for (int i = 0; i < 4; i++) {
            float cr = cS[ty * 4 + i];
#pragma unroll
            for (int j = 0; j < 4; j++) Oa[i][j] *= cr;
        }
        Ob *= cS[obq];

        // ---- phase 2a: O[q][0..63] += P V  (4x4 per thread) ----
        const float* prow = Ps + (ty * 4) * LDC;
        const float* vrow = VsT + (tx * 4) * LDC;
#pragma unroll
        for (int k4 = 0; k4 < TK; k4 += 4) {
            float4 pv[4], vv[4];
#pragma unroll
            for (int i = 0; i < 4; i++) pv[i] = *(const float4*)(prow + i * LDC + k4);
#pragma unroll
            for (int j = 0; j < 4; j++) vv[j] = *(const float4*)(vrow + j * LDC + k4);
#pragma unroll
            for (int i = 0; i < 4; i++)
#pragma unroll
                for (int j = 0; j < 4; j++)
                    Oa[i][j] += pv[i].x * vv[j].x + pv[i].y * vv[j].y
                              + pv[i].z * vv[j].z + pv[i].w * vv[j].w;
        }

        // ---- phase 2b: coords + weight channels (64..67) ----
        {
            const float* pb = Ps + obq * LDC;
            const float* vb = VsT + obc * LDC;
#pragma unroll
            for (int k4 = 0; k4 < TK; k4 += 4) {
                float4 p = *(const float4*)(pb + k4);
                float4 v = *(const float4*)(vb + k4);
                Ob += p.x * v.x + p.y * v.y + p.z * v.z + p.w * v.w;
            }
        }
        __syncthreads();
    }

    // ---- write partials: layout [blk][cv][q] for coalesced combine reads ----
    const int blk = (b * 16 + qt) * KSPLIT + ks;
    float* Op = g_part + (size_t)blk * 64 * 68;
#pragma unroll
    for (int i = 0; i < 4; i++)
#pragma unroll
        for (int j = 0; j < 4; j++)
            Op[(tx * 4 + j) * 64 + ty * 4 + i] = Oa[i][j];
    Op[obc * 64 + obq] = Ob;
    if (tid < 64) { g_pm[blk * 64 + tid] = mS[tid]; g_pl[blk * 64 + tid] = lS[tid]; }
}

// ---------------------------------------------------------------------------
// Combine split-KV partials + epilogue (zn descs, 2D projection, outputs)
// ---------------------------------------------------------------------------
__global__ void combine_kernel(float* __restrict__ out) {
    int gq = blockIdx.x * blockDim.x + threadIdx.x;   // 4096 queries
    int b = gq >> 10, n = gq & 1023;
    int bqt = gq >> 6;       // (b*16 + qtile)
    int r = gq & 63;

    float Mx = -CUDART_INF_F;
#pragma unroll
    for (int s = 0; s < KSPLIT; s++)
        Mx = fmaxf(Mx, g_pm[(bqt * KSPLIT + s) * 64 + r]);

    float val[68];
#pragma unroll
    for (int ch = 0; ch < 68; ch++) val[ch] = 0.f;
    float L = 0.f;
    for (int s = 0; s < KSPLIT; s++) {
        int blk = bqt * KSPLIT + s;
        float w = __expf(SCALE * (g_pm[blk * 64 + r] - Mx));
        L += g_pl[blk * 64 + r] * w;
        const float* Op = g_part + (size_t)blk * 64 * 68;
#pragma unroll
        for (int ch = 0; ch < 68; ch++) val[ch] += Op[ch * 64 + r] * w;
    }
    float invL = 1.f / L;
#pragma unroll
    for (int ch = 0; ch < 68; ch++) val[ch] *= invL;

    float x = val[64], y = val[65], z = val[66], wgt = val[67];

    // zn of desc output channels (ddof=1)
    float sum = 0.f;
#pragma unroll
    for (int c = 0; c < 64; c++) sum += val[c];
    float mean = sum * (1.f / 64.f);
    float var = 0.f;
#pragma unroll
    for (int c = 0; c < 64; c++) { float d = val[c] - mean; var += d * d; }
    float inv = rsqrtf(var * (1.f / 63.f));

    // Output layout (flattened concat of reference tuple, all float32):
    // coords (B,3,N) @0 | weights (B,1,N) @12288 | descs (B,64,N) @16384
    // | 2D (B,N,2) @278528 | valid (B,1,N) @286720
    out[(b * 3 + 0) * 1024 + n] = x;
    out[(b * 3 + 1) * 1024 + n] = y;
    out[(b * 3 + 2) * 1024 + n] = z;
    out[12288 + b * 1024 + n] = wgt;
#pragma unroll
    for (int c = 0; c < 64; c++)
        out[16384 + (b * 64 + c) * 1024 + n] = (val[c] - mean) * inv;

    float rr = sqrtf(x * x + y * y + z * z);
    float az = atan2f(y, x);
    float el = asinf(z / (rr + 1e-12f));
    float u = 0.5f * (1.0f - az * (1.0f / CUDART_PI_F)) * 1024.0f;
    float v = (1.0f - (el + 0.4363323129985824f) * (1.0f / 0.4886921905584123f)) * 64.0f;
    u = fminf(fmaxf(u, 0.f), 1023.f);
    v = fminf(fmaxf(v, 0.f), 63.f);
    out[278528 + gq * 2 + 0] = u;
    out[278528 + gq * 2 + 1] = v;

    out[286720 + b * 1024 + n] = 1.0f;   // valid_pts
}

// ---------------------------------------------------------------------------
extern "C" void kernel_launch(void* const* d_in, const int* in_sizes, int n_in,
                              void* d_out, int out_size) {
    // metadata order: src_coords (unused), tgt_coords, tgt_weights, src_desc, tgt_desc
    const float* tgt_coords = (const float*)d_in[1];
    const float* tgt_w      = (const float*)d_in[2];
    const float* src_desc   = (const float*)d_in[3];
    const float* tgt_desc   = (const float*)d_in[4];
    float* out = (float*)d_out;

    const size_t smem = (size_t)(3 * TQ * LDC + 68 * LDC + 3 * 64) * sizeof(float); // ~71.5 KB
    cudaFuncSetAttribute(attn_kernel, cudaFuncAttributeMaxDynamicSharedMemorySize, (int)smem);

    norm_src_kernel<<<16, 256>>>(src_desc);
    norm_tgt_kernel<<<1024, 256>>>(tgt_desc, tgt_coords, tgt_w);
    dim3 grid(KSPLIT, NN / TQ, BB);
    attn_kernel<<<grid, 256, smem>>>();
    combine_kernel<<<16, 256>>>(out);
}

// round 4
// speedup vs baseline: 1.0038x; 1.0038x over previous
#include <cuda_runtime.h>
#include <math_constants.h>

// Problem constants
#define BB    4
#define NN    1024      // src points per batch
#define MM    65536     // H*W target points per batch
#define CC    64        // desc channels
#define VCH   72        // padded V row stride (0..63 raw desc, 64..66 coords, 67 weight)
#define SCALE 1.5625f   // 1/(C*TEMP) = 1/(64*0.01)

#define TQ 64
#define TK 64
#define LDC 68          // padded smem row stride (floats), 272B = 16B aligned, conflict-free
#define KSPLIT 16
#define NBLK (BB*16*KSPLIT)   // 4 * (1024/64) * 16 = 1024 partial blocks

// Scratch (static __device__ arrays: allocation-free per harness rules)
__device__ float g_Q[BB*NN*CC];                       //  1 MB  [b][n][c]
__device__ float g_K[(size_t)BB*MM*CC];               // 64 MB  [b][m][c]
__device__ float g_V[(size_t)BB*MM*VCH];              // 75 MB  [b][m][cv]
__device__ float g_part[(size_t)NBLK*64*68];          // 18 MB  [blk][cv][q]
__device__ float g_pm[NBLK*64];
__device__ float g_pl[NBLK*64];

// ---------------------------------------------------------------------------
// Normalize src_desc -> Q  (zn over channel dim, ddof=1)
// ---------------------------------------------------------------------------
__global__ void norm_src_kernel(const float* __restrict__ src_desc) {
    int gid = blockIdx.x * blockDim.x + threadIdx.x;   // 4096 = B*N
    int b = gid >> 10, n = gid & 1023;
    const float* p = src_desc + (size_t)b * CC * NN + n;
    float xs[CC];
    float sum = 0.f;
#pragma unroll
    for (int c = 0; c < CC; c++) { xs[c] = p[c * NN]; sum += xs[c]; }
    float mean = sum * (1.f / 64.f);
    float var = 0.f;
#pragma unroll
    for (int c = 0; c < CC; c++) { float d = xs[c] - mean; var += d * d; }
    float inv = rsqrtf(var * (1.f / 63.f));
    float* q = g_Q + (size_t)gid * CC;
#pragma unroll
    for (int c = 0; c < CC; c++) q[c] = (xs[c] - mean) * inv;
}

// ---------------------------------------------------------------------------
// Normalize tgt_desc -> K ; pack V = [raw desc | coords | weight]
// ---------------------------------------------------------------------------
__global__ void norm_tgt_kernel(const float* __restrict__ tgt_desc,
                                const float* __restrict__ tgt_coords,
                                const float* __restrict__ tgt_w) {
    int gid = blockIdx.x * blockDim.x + threadIdx.x;   // 262144 = B*M
    int b = gid >> 16, m = gid & 65535;
    const float* p = tgt_desc + (size_t)b * CC * MM + m;
    float xs[CC];
    float sum = 0.f;
#pragma unroll
    for (int c = 0; c < CC; c++) { xs[c] = p[(size_t)c * MM]; sum += xs[c]; }
    float mean = sum * (1.f / 64.f);
    float var = 0.f;
#pragma unroll
    for (int c = 0; c < CC; c++) { float d = xs[c] - mean; var += d * d; }
    float inv = rsqrtf(var * (1.f / 63.f));
    float* kk = g_K + (size_t)gid * CC;
    float* vv = g_V + (size_t)gid * VCH;
#pragma unroll
    for (int c = 0; c < CC; c++) { kk[c] = (xs[c] - mean) * inv; vv[c] = xs[c]; }
    vv[64] = tgt_coords[(size_t)(b * 3 + 0) * MM + m];
    vv[65] = tgt_coords[(size_t)(b * 3 + 1) * MM + m];
    vv[66] = tgt_coords[(size_t)(b * 3 + 2) * MM + m];
    vv[67] = tgt_w[(size_t)b * MM + m];
}

// ---------------------------------------------------------------------------
// Fused flash attention, fp32, 4x4 register tiles, split-KV partials
// grid: (KSPLIT, N/TQ, B), block: 256
// ---------------------------------------------------------------------------
__global__ __launch_bounds__(256, 2) void attn_kernel() {
    extern __shared__ float sm[];
    float* Qs  = sm;                 // [64][LDC]  (q, c)
    float* Ks  = Qs  + TQ * LDC;     // [64][LDC]  (k, c)
    float* Ps  = Ks  + TK * LDC;     // [64][LDC]  (q, k)
    float* VsT = Ps  + TQ * LDC;     // [68][LDC]  (cv, k)
    float* mS  = VsT + 68 * LDC;     // [64]
    float* lS  = mS + 64;            // [64]
    float* cS  = lS + 64;            // [64]

    const int ks = blockIdx.x;       // key split 0..15
    const int qt = blockIdx.y;       // q tile 0..15
    const int b  = blockIdx.z;
    const int tid = threadIdx.x;
    const int ty = tid >> 4, tx = tid & 15;

    // Load Q tile (coalesced)
    const float* Qg = g_Q + ((size_t)b * NN + qt * TQ) * CC;
    for (int i = tid; i < TQ * CC; i += 256) {
        int q = i >> 6, c = i & 63;
        Qs[q * LDC + c] = Qg[q * CC + c];
    }
    if (tid < 64) { mS[tid] = -CUDART_INF_F; lS[tid] = 0.f; }

    float Oa[4][4];
#pragma unroll
    for (int i = 0; i < 4; i++)
#pragma unroll
        for (int j = 0; j < 4; j++) Oa[i][j] = 0.f;
    float Ob = 0.f;
    const int obq = tid >> 2;            // phase-2b query
    const int obc = 64 + (tid & 3);      // phase-2b channel (coords/weight)

    const int kbase = ks * (MM / KSPLIT);
    const float* Kg = g_K + ((size_t)b * MM + kbase) * CC;
    const float* Vg = g_V + ((size_t)b * MM + kbase) * VCH;

    __syncthreads();

    for (int kt = 0; kt < (MM / KSPLIT) / TK; kt++) {
        // ---- load K tile and V tile (V transposed to [cv][k]) ----
        const float* Kt = Kg + (size_t)(kt * TK) * CC;
        for (int i = tid; i < TK * CC; i += 256) {
            int k = i >> 6, c = i & 63;
            Ks[k * LDC + c] = Kt[k * CC + c];
        }
        const float* Vt = Vg + (size_t)(kt * TK) * VCH;
        for (int i = tid; i < TK * 68; i += 256) {
            int k = i / 68, cv = i - k * 68;
            VsT[cv * LDC + k] = Vt[k * VCH + cv];
        }
        __syncthreads();

        // ---- phase 1: S = Q K^T (4x4 per thread) ----
        float acc[4][4];
#pragma unroll
        for (int i = 0; i < 4; i++)
#pragma unroll
            for (int j = 0; j < 4; j++) acc[i][j] = 0.f;

        const float* qrow = Qs + (ty * 4) * LDC;
        const float* krow = Ks + (tx * 4) * LDC;
#pragma unroll
        for (int c4 = 0; c4 < CC; c4 += 4) {
            float4 av[4], bv[4];
#pragma unroll
            for (int i = 0; i < 4; i++) av[i] = *(const float4*)(qrow + i * LDC + c4);
#pragma unroll
            for (int j = 0; j < 4; j++) bv[j] = *(const float4*)(krow + j * LDC + c4);
#pragma unroll
            for (int i = 0; i < 4; i++)
#pragma unroll
                for (int j = 0; j < 4; j++)
                    acc[i][j] += av[i].x * bv[j].x + av[i].y * bv[j].y
                               + av[i].z * bv[j].z + av[i].w * bv[j].w;
        }

        // ---- online softmax bookkeeping (row groups owned by half-warps) ----
#pragma unroll
        for (int i = 0; i < 4; i++) {
            float rm = fmaxf(fmaxf(acc[i][0], acc[i][1]), fmaxf(acc[i][2], acc[i][3]));
#pragma unroll
            for (int off = 8; off > 0; off >>= 1)
                rm = fmaxf(rm, __shfl_xor_sync(0xffffffffu, rm, off));
            int q = ty * 4 + i;
            float mo = mS[q];
            float mn = fmaxf(mo, rm);
            float corr = __expf(SCALE * (mo - mn));   // -inf -> 0 on first tile
            float rs = 0.f;
#pragma unroll
            for (int j = 0; j < 4; j++) {
                float p = __expf(SCALE * (acc[i][j] - mn));
                Ps[q * LDC + tx * 4 + j] = p;
                rs += p;
            }
#pragma unroll
            for (int off = 8; off > 0; off >>= 1)
                rs += __shfl_xor_sync(0xffffffffu, rs, off);
            if (tx == 0) { mS[q] = mn; lS[q] = lS[q] * corr + rs; cS[q] = corr; }
        }
        __syncthreads();

        // ---- rescale accumulators ----
#pragma unroll
        for (int i = 0; i < 4; i++) {
            float cr = cS[ty * 4 + i];
#pragma unroll
            for (int j = 0; j < 4; j++) Oa[i][j] *= cr;
        }
        Ob *= cS[obq];

        // ---- phase 2a: O[q][0..63] += P V  (4x4 per thread) ----
        const float* prow = Ps + (ty * 4) * LDC;
        const float* vrow = VsT + (tx * 4) * LDC;
#pragma unroll
        for (int k4 = 0; k4 < TK; k4 += 4) {
            float4 pv[4], vv[4];
#pragma unroll
            for (int i = 0; i < 4; i++) pv[i] = *(const float4*)(prow + i * LDC + k4);
#pragma unroll
            for (int j = 0; j < 4; j++) vv[j] = *(const float4*)(vrow + j * LDC + k4);
#pragma unroll
            for (int i = 0; i < 4; i++)
#pragma unroll
                for (int j = 0; j < 4; j++)
                    Oa[i][j] += pv[i].x * vv[j].x + pv[i].y * vv[j].y
                              + pv[i].z * vv[j].z + pv[i].w * vv[j].w;
        }

        // ---- phase 2b: coords + weight channels (64..67) ----
        {
            const float* pb = Ps + obq * LDC;
            const float* vb = VsT + obc * LDC;
#pragma unroll
            for (int k4 = 0; k4 < TK; k4 += 4) {
                float4 p = *(const float4*)(pb + k4);
                float4 v = *(const float4*)(vb + k4);
                Ob += p.x * v.x + p.y * v.y + p.z * v.z + p.w * v.w;
            }
        }
        __syncthreads();
    }

    // ---- write partials: layout [blk][cv][q] for coalesced combine reads ----
    const int blk = (b * 16 + qt) * KSPLIT + ks;
    float* Op = g_part + (size_t)blk * 64 * 68;
#pragma unroll
    for (int i = 0; i < 4; i++)
#pragma unroll
        for (int j = 0; j < 4; j++)
            Op[(tx * 4 + j) * 64 + ty * 4 + i] = Oa[i][j];
    Op[obc * 64 + obq] = Ob;
    if (tid < 64) { g_pm[blk * 64 + tid] = mS[tid]; g_pl[blk * 64 + tid] = lS[tid]; }
}

// ---------------------------------------------------------------------------
// Combine split-KV partials + epilogue (zn descs, 2D projection, outputs)
// ---------------------------------------------------------------------------
__global__ void combine_kernel(float* __restrict__ out) {
    int gq = blockIdx.x * blockDim.x + threadIdx.x;   // 4096 queries
    int b = gq >> 10, n = gq & 1023;
    int bqt = gq >> 6;       // (b*16 + qtile)
    int r = gq & 63;

    float Mx = -CUDART_INF_F;
#pragma unroll
    for (int s = 0; s < KSPLIT; s++)
        Mx = fmaxf(Mx, g_pm[(bqt * KSPLIT + s) * 64 + r]);

    float val[68];
#pragma unroll
    for (int ch = 0; ch < 68; ch++) val[ch] = 0.f;
    float L = 0.f;
    for (int s = 0; s < KSPLIT; s++) {
        int blk = bqt * KSPLIT + s;
        float w = __expf(SCALE * (g_pm[blk * 64 + r] - Mx));
        L += g_pl[blk * 64 + r] * w;
        const float* Op = g_part + (size_t)blk * 64 * 68;
#pragma unroll
        for (int ch = 0; ch < 68; ch++) val[ch] += Op[ch * 64 + r] * w;
    }
    float invL = 1.f / L;
#pragma unroll
    for (int ch = 0; ch < 68; ch++) val[ch] *= invL;

    float x = val[64], y = val[65], z = val[66], wgt = val[67];

    // zn of desc output channels (ddof=1)
    float sum = 0.f;
#pragma unroll
    for (int c = 0; c < 64; c++) sum += val[c];
    float mean = sum * (1.f / 64.f);
    float var = 0.f;
#pragma unroll
    for (int c = 0; c < 64; c++) { float d = val[c] - mean; var += d * d; }
    float inv = rsqrtf(var * (1.f / 63.f));

    // Output layout (flattened concat of reference tuple, all float32):
    // coords (B,3,N) @0 | weights (B,1,N) @12288 | descs (B,64,N) @16384
    // | 2D (B,N,2) @278528 | valid (B,1,N) @286720
    out[(b * 3 + 0) * 1024 + n] = x;
    out[(b * 3 + 1) * 1024 + n] = y;
    out[(b * 3 + 2) * 1024 + n] = z;
    out[12288 + b * 1024 + n] = wgt;
#pragma unroll
    for (int c = 0; c < 64; c++)
        out[16384 + (b * 64 + c) * 1024 + n] = (val[c] - mean) * inv;

    float rr = sqrtf(x * x + y * y + z * z);
    float az = atan2f(y, x);
    float el = asinf(z / (rr + 1e-12f));
    float u = 0.5f * (1.0f - az * (1.0f / CUDART_PI_F)) * 1024.0f;
    float v = (1.0f - (el + 0.4363323129985824f) * (1.0f / 0.4886921905584123f)) * 64.0f;
    u = fminf(fmaxf(u, 0.f), 1023.f);
    v = fminf(fmaxf(v, 0.f), 63.f);
    out[278528 + gq * 2 + 0] = u;
    out[278528 + gq * 2 + 1] = v;

    out[286720 + b * 1024 + n] = 1.0f;   // valid_pts
}

// ---------------------------------------------------------------------------
extern "C" void kernel_launch(void* const* d_in, const int* in_sizes, int n_in,
                              void* d_out, int out_size) {
    // metadata order: src_coords (unused), tgt_coords, tgt_weights, src_desc, tgt_desc
    const float* tgt_coords = (const float*)d_in[1];
    const float* tgt_w      = (const float*)d_in[2];
    const float* src_desc   = (const float*)d_in[3];
    const float* tgt_desc   = (const float*)d_in[4];
    float* out = (float*)d_out;

    const size_t smem = (size_t)(3 * TQ * LDC + 68 * LDC + 3 * 64) * sizeof(float); // ~71.5 KB
    cudaFuncSetAttribute(attn_kernel, cudaFuncAttributeMaxDynamicSharedMemorySize, (int)smem);

    norm_src_kernel<<<16, 256>>>(src_desc);
    norm_tgt_kernel<<<1024, 256>>>(tgt_desc, tgt_coords, tgt_w);
    dim3 grid(KSPLIT, NN / TQ, BB);
    attn_kernel<<<grid, 256, smem>>>();
    combine_kernel<<<16, 256>>>(out);
}

// round 6
// speedup vs baseline: 1.0057x; 1.0019x over previous
#include <cuda_runtime.h>
#include <math_constants.h>

// Problem constants
#define BB    4
#define NN    1024      // src points per batch
#define MM    65536     // H*W target points per batch
#define CC    64        // desc channels
#define VCH   72        // padded V row stride (0..63 raw desc, 64..66 coords, 67 weight)
#define SCALE 1.5625f   // 1/(C*TEMP) = 1/(64*0.01)

#define TQ 64
#define TK 64
#define LDC 68          // padded smem row stride (floats), 272B = 16B aligned, conflict-free
#define KSPLIT 16
#define NBLK (BB*16*KSPLIT)   // 4 * (1024/64) * 16 = 1024 partial blocks

// Scratch (static __device__ arrays: allocation-free per harness rules)
__device__ float g_Q[BB*NN*CC];                       //  1 MB  [b][n][c]
__device__ float g_K[(size_t)BB*MM*CC];               // 64 MB  [b][m][c]
__device__ float g_V[(size_t)BB*MM*VCH];              // 75 MB  [b][m][cv]
__device__ float g_part[(size_t)NBLK*64*68];          // 18 MB  [blk][cv][q]
__device__ float g_pm[NBLK*64];
__device__ float g_pl[NBLK*64];

// ---------------------------------------------------------------------------
// Normalize src_desc -> Q  (zn over channel dim, ddof=1)
// ---------------------------------------------------------------------------
__global__ void norm_src_kernel(const float* __restrict__ src_desc) {
    int gid = blockIdx.x * blockDim.x + threadIdx.x;   // 4096 = B*N
    int b = gid >> 10, n = gid & 1023;
    const float* p = src_desc + (size_t)b * CC * NN + n;
    float xs[CC];
    float sum = 0.f;
#pragma unroll
    for (int c = 0; c < CC; c++) { xs[c] = p[c * NN]; sum += xs[c]; }
    float mean = sum * (1.f / 64.f);
    float var = 0.f;
#pragma unroll
    for (int c = 0; c < CC; c++) { float d = xs[c] - mean; var += d * d; }
    float inv = rsqrtf(var * (1.f / 63.f));
    float* q = g_Q + (size_t)gid * CC;
#pragma unroll
    for (int c = 0; c < CC; c++) q[c] = (xs[c] - mean) * inv;
}

// ---------------------------------------------------------------------------
// Normalize tgt_desc -> K ; pack V = [raw desc | coords | weight]
// ---------------------------------------------------------------------------
__global__ void norm_tgt_kernel(const float* __restrict__ tgt_desc,
                                const float* __restrict__ tgt_coords,
                                const float* __restrict__ tgt_w) {
    int gid = blockIdx.x * blockDim.x + threadIdx.x;   // 262144 = B*M
    int b = gid >> 16, m = gid & 65535;
    const float* p = tgt_desc + (size_t)b * CC * MM + m;
    float xs[CC];
    float sum = 0.f;
#pragma unroll
    for (int c = 0; c < CC; c++) { xs[c] = p[(size_t)c * MM]; sum += xs[c]; }
    float mean = sum * (1.f / 64.f);
    float var = 0.f;
#pragma unroll
    for (int c = 0; c < CC; c++) { float d = xs[c] - mean; var += d * d; }
    float inv = rsqrtf(var * (1.f / 63.f));
    float* kk = g_K + (size_t)gid * CC;
    float* vv = g_V + (size_t)gid * VCH;
#pragma unroll
    for (int c = 0; c < CC; c++) { kk[c] = (xs[c] - mean) * inv; vv[c] = xs[c]; }
    vv[64] = tgt_coords[(size_t)(b * 3 + 0) * MM + m];
    vv[65] = tgt_coords[(size_t)(b * 3 + 1) * MM + m];
    vv[66] = tgt_coords[(size_t)(b * 3 + 2) * MM + m];
    vv[67] = tgt_w[(size_t)b * MM + m];
}

// ---------------------------------------------------------------------------
// Fused flash attention, fp32, 4x4 register tiles, split-KV partials
// grid: (KSPLIT, N/TQ, B), block: 256
// ---------------------------------------------------------------------------
__global__ __launch_bounds__(256, 2) void attn_kernel() {
    extern __shared__ float sm[];
    float* Qs  = sm;                 // [64][LDC]  (q, c)
    float* Ks  = Qs  + TQ * LDC;     // [64][LDC]  (k, c)
    float* Ps  = Ks  + TK * LDC;     // [64][LDC]  (q, k)
    float* VsT = Ps  + TQ * LDC;     // [68][LDC]  (cv, k)
    float* mS  = VsT + 68 * LDC;     // [64]
    float* lS  = mS + 64;            // [64]
    float* cS  = lS + 64;            // [64]

    const int ks = blockIdx.x;       // key split 0..15
    const int qt = blockIdx.y;       // q tile 0..15
    const int b  = blockIdx.z;
    const int tid = threadIdx.x;
    const int ty = tid >> 4, tx = tid & 15;

    // Load Q tile (coalesced)
    const float* Qg = g_Q + ((size_t)b * NN + qt * TQ) * CC;
    for (int i = tid; i < TQ * CC; i += 256) {
        int q = i >> 6, c = i & 63;
        Qs[q * LDC + c] = Qg[q * CC + c];
    }
    if (tid < 64) { mS[tid] = -CUDART_INF_F; lS[tid] = 0.f; }

    float Oa[4][4];
#pragma unroll
    for (int i = 0; i < 4; i++)
#pragma unroll
        for (int j = 0; j < 4; j++) Oa[i][j] = 0.f;
    float Ob = 0.f;
    const int obq = tid >> 2;            // phase-2b query
    const int obc = 64 + (tid & 3);      // phase-2b channel (coords/weight)

    const int kbase = ks * (MM / KSPLIT);
    const float* Kg = g_K + ((size_t)b * MM + kbase) * CC;
    const float* Vg = g_V + ((size_t)b * MM + kbase) * VCH;

    __syncthreads();

    for (int kt = 0; kt < (MM / KSPLIT) / TK; kt++) {
        // ---- load K tile and V tile (V transposed to [cv][k]) ----
        const float* Kt = Kg + (size_t)(kt * TK) * CC;
        for (int i = tid; i < TK * CC; i += 256) {
            int k = i >> 6, c = i & 63;
            Ks[k * LDC + c] = Kt[k * CC + c];
        }
        const float* Vt = Vg + (size_t)(kt * TK) * VCH;
        for (int i = tid; i < TK * 68; i += 256) {
            int k = i / 68, cv = i - k * 68;
            VsT[cv * LDC + k] = Vt[k * VCH + cv];
        }
        __syncthreads();

        // ---- phase 1: S = Q K^T (4x4 per thread) ----
        float acc[4][4];
#pragma unroll
        for (int i = 0; i < 4; i++)
#pragma unroll
            for (int j = 0; j < 4; j++) acc[i][j] = 0.f;

        const float* qrow = Qs + (ty * 4) * LDC;
        const float* krow = Ks + (tx * 4) * LDC;
#pragma unroll
        for (int c4 = 0; c4 < CC; c4 += 4) {
            float4 av[4], bv[4];
#pragma unroll
            for (int i = 0; i < 4; i++) av[i] = *(const float4*)(qrow + i * LDC + c4);
#pragma unroll
            for (int j = 0; j < 4; j++) bv[j] = *(const float4*)(krow + j * LDC + c4);
#pragma unroll
            for (int i = 0; i < 4; i++)
#pragma unroll
                for (int j = 0; j < 4; j++)
                    acc[i][j] += av[i].x * bv[j].x + av[i].y * bv[j].y
                               + av[i].z * bv[j].z + av[i].w * bv[j].w;
        }

        // ---- online softmax bookkeeping (row groups owned by half-warps) ----
#pragma unroll
        for (int i = 0; i < 4; i++) {
            float rm = fmaxf(fmaxf(acc[i][0], acc[i][1]), fmaxf(acc[i][2], acc[i][3]));
#pragma unroll
            for (int off = 8; off > 0; off >>= 1)
                rm = fmaxf(rm, __shfl_xor_sync(0xffffffffu, rm, off));
            int q = ty * 4 + i;
            float mo = mS[q];
            float mn = fmaxf(mo, rm);
            float corr = __expf(SCALE * (mo - mn));   // -inf -> 0 on first tile
            float rs = 0.f;
#pragma unroll
            for (int j = 0; j < 4; j++) {
                float p = __expf(SCALE * (acc[i][j] - mn));
                Ps[q * LDC + tx * 4 + j] = p;
                rs += p;
            }
#pragma unroll
            for (int off = 8; off > 0; off >>= 1)
                rs += __shfl_xor_sync(0xffffffffu, rs, off);
            if (tx == 0) { mS[q] = mn; lS[q] = lS[q] * corr + rs; cS[q] = corr; }
        }
        __syncthreads();

        // ---- rescale accumulators ----
#pragma unroll
        for (int i = 0; i < 4; i++) {
            float cr = cS[ty * 4 + i];
#pragma unroll
            for (int j = 0; j < 4; j++) Oa[i][j] *= cr;
        }
        Ob *= cS[obq];

        // ---- phase 2a: O[q][0..63] += P V  (4x4 per thread) ----
        const float* prow = Ps + (ty * 4) * LDC;
        const float* vrow = VsT + (tx * 4) * LDC;
#pragma unroll
        for (int k4 = 0; k4 < TK; k4 += 4) {
            float4 pv[4], vv[4];
#pragma unroll
            for (int i = 0; i < 4; i++) pv[i] = *(const float4*)(prow + i * LDC + k4);
#pragma unroll
            for (int j = 0; j < 4; j++) vv[j] = *(const float4*)(vrow + j * LDC + k4);
#pragma unroll
            for (int i = 0; i < 4; i++)
#pragma unroll
                for (int j = 0; j < 4; j++)
                    Oa[i][j] += pv[i].x * vv[j].x + pv[i].y * vv[j].y
                              + pv[i].z * vv[j].z + pv[i].w * vv[j].w;
        }

        // ---- phase 2b: coords + weight channels (64..67) ----
        {
            const float* pb = Ps + obq * LDC;
            const float* vb = VsT + obc * LDC;
#pragma unroll
            for (int k4 = 0; k4 < TK; k4 += 4) {
                float4 p = *(const float4*)(pb + k4);
                float4 v = *(const float4*)(vb + k4);
                Ob += p.x * v.x + p.y * v.y + p.z * v.z + p.w * v.w;
            }
        }
        __syncthreads();
    }

    // ---- write partials: layout [blk][cv][q] for coalesced combine reads ----
    const int blk = (b * 16 + qt) * KSPLIT + ks;
    float* Op = g_part + (size_t)blk * 64 * 68;
#pragma unroll
    for (int i = 0; i < 4; i++)
#pragma unroll
        for (int j = 0; j < 4; j++)
            Op[(tx * 4 + j) * 64 + ty * 4 + i] = Oa[i][j];
    Op[obc * 64 + obq] = Ob;
    if (tid < 64) { g_pm[blk * 64 + tid] = mS[tid]; g_pl[blk * 64 + tid] = lS[tid]; }
}

// ---------------------------------------------------------------------------
// Combine split-KV partials + epilogue (zn descs, 2D projection, outputs)
// ---------------------------------------------------------------------------
__global__ void combine_kernel(float* __restrict__ out) {
    int gq = blockIdx.x * blockDim.x + threadIdx.x;   // 4096 queries
    int b = gq >> 10, n = gq & 1023;
    int bqt = gq >> 6;       // (b*16 + qtile)
    int r = gq & 63;

    float Mx = -CUDART_INF_F;
#pragma unroll
    for (int s = 0; s < KSPLIT; s++)
        Mx = fmaxf(Mx, g_pm[(bqt * KSPLIT + s) * 64 + r]);

    float val[68];
#pragma unroll
    for (int ch = 0; ch < 68; ch++) val[ch] = 0.f;
    float L = 0.f;
    for (int s = 0; s < KSPLIT; s++) {
        int blk = bqt * KSPLIT + s;
        float w = __expf(SCALE * (g_pm[blk * 64 + r] - Mx));
        L += g_pl[blk * 64 + r] * w;
        const float* Op = g_part + (size_t)blk * 64 * 68;
#pragma unroll
        for (int ch = 0; ch < 68; ch++) val[ch] += Op[ch * 64 + r] * w;
    }
    float invL = 1.f / L;
#pragma unroll
    for (int ch = 0; ch < 68; ch++) val[ch] *= invL;

    float x = val[64], y = val[65], z = val[66], wgt = val[67];

    // zn of desc output channels (ddof=1)
    float sum = 0.f;
#pragma unroll
    for (int c = 0; c < 64; c++) sum += val[c];
    float mean = sum * (1.f / 64.f);
    float var = 0.f;
#pragma unroll
    for (int c = 0; c < 64; c++) { float d = val[c] - mean; var += d * d; }
    float inv = rsqrtf(var * (1.f / 63.f));

    // Output layout (flattened concat of reference tuple, all float32):
    // coords (B,3,N) @0 | weights (B,1,N) @12288 | descs (B,64,N) @16384
    // | 2D (B,N,2) @278528 | valid (B,1,N) @286720
    out[(b * 3 + 0) * 1024 + n] = x;
    out[(b * 3 + 1) * 1024 + n] = y;
    out[(b * 3 + 2) * 1024 + n] = z;
    out[12288 + b * 1024 + n] = wgt;
#pragma unroll
    for (int c = 0; c < 64; c++)
        out[16384 + (b * 64 + c) * 1024 + n] = (val[c] - mean) * inv;

    float rr = sqrtf(x * x + y * y + z * z);
    float az = atan2f(y, x);
    float el = asinf(z / (rr + 1e-12f));
    float u = 0.5f * (1.0f - az * (1.0f / CUDART_PI_F)) * 1024.0f;
    float v = (1.0f - (el + 0.4363323129985824f) * (1.0f / 0.4886921905584123f)) * 64.0f;
    u = fminf(fmaxf(u, 0.f), 1023.f);
    v = fminf(fmaxf(v, 0.f), 63.f);
    out[278528 + gq * 2 + 0] = u;
    out[278528 + gq * 2 + 1] = v;

    out[286720 + b * 1024 + n] = 1.0f;   // valid_pts
}

// ---------------------------------------------------------------------------
extern "C" void kernel_launch(void* const* d_in, const int* in_sizes, int n_in,
                              void* d_out, int out_size) {
    // metadata order: src_coords (unused), tgt_coords, tgt_weights, src_desc, tgt_desc
    const float* tgt_coords = (const float*)d_in[1];
    const float* tgt_w      = (const float*)d_in[2];
    const float* src_desc   = (const float*)d_in[3];
    const float* tgt_desc   = (const float*)d_in[4];
    float* out = (float*)d_out;

    const size_t smem = (size_t)(3 * TQ * LDC + 68 * LDC + 3 * 64) * sizeof(float); // ~71.5 KB
    cudaFuncSetAttribute(attn_kernel, cudaFuncAttributeMaxDynamicSharedMemorySize, (int)smem);

    norm_src_kernel<<<16, 256>>>(src_desc);
    norm_tgt_kernel<<<1024, 256>>>(tgt_desc, tgt_coords, tgt_w);
    dim3 grid(KSPLIT, NN / TQ, BB);
    attn_kernel<<<grid, 256, smem>>>();
    combine_kernel<<<16, 256>>>(out);
}

// round 8
// speedup vs baseline: 9.8204x; 9.7651x over previous
#include <cuda_runtime.h>
#include <cuda_fp16.h>
#include <cuda_bf16.h>
#include <math_constants.h>
#include <cstdint>

#define BB 4
#define NN 1024
#define MM 65536
#define SCALE 1.5625f                 // 1/(64*0.01)
#define K2 2.2542110013900995f        // SCALE * log2(e)
#define KSPLIT 4
#define TK 64
#define NCHUNK (MM/KSPLIT/TK)         // 256
#define NBLK (BB*8*KSPLIT)            // 128

// ------------------------------------------------------------------ scratch
__device__ __nv_bfloat16 g_Qh[BB*NN*64];            // [b*1024+n][64]
__device__ __nv_bfloat16 g_Ql[BB*NN*64];
__device__ __nv_bfloat16 g_Kh[(size_t)BB*MM*64];    // [(b<<16)+m][64]
__device__ __nv_bfloat16 g_Kl[(size_t)BB*MM*64];
__device__ __half        g_Vt[(size_t)BB*72*MM];    // [b*72+ch][m]; ch68=ones, 69-71 zero (.bss)
__device__ float g_part[(size_t)NBLK*69*128];       // [blk][ch][r]
__device__ float g_pm[NBLK*128];

// ------------------------------------------------------------------ helpers
__device__ __forceinline__ uint32_t smem_u32(const void* p) {
    uint32_t a;
    asm("{ .reg .u64 t; cvta.to.shared.u64 t, %1; cvt.u32.u64 %0, t; }" : "=r"(a) : "l"(p));
    return a;
}
__device__ __forceinline__ void cpa16(void* dst, const void* src) {
    uint32_t d = smem_u32(dst);
    asm volatile("cp.async.cg.shared.global [%0], [%1], 16;" :: "r"(d), "l"(src) : "memory");
}
#define CPA_COMMIT() asm volatile("cp.async.commit_group;" ::: "memory")
#define CPA_WAIT(n)  asm volatile("cp.async.wait_group %0;" :: "n"(n) : "memory")

__device__ __forceinline__ float ex2(float x) {
    float y; asm("ex2.approx.ftz.f32 %0, %1;" : "=f"(y) : "f"(x)); return y;
}
__device__ __forceinline__ uint32_t pkh2(float hi, float lo) {
    uint32_t d; asm("cvt.rn.f16x2.f32 %0, %1, %2;" : "=r"(d) : "f"(hi), "f"(lo)); return d;
}
__device__ __forceinline__ void mma_bf16(float4& d, const uint32_t* a, uint32_t b0, uint32_t b1) {
    asm volatile("mma.sync.aligned.m16n8k16.row.col.f32.bf16.bf16.f32 "
                 "{%0,%1,%2,%3},{%4,%5,%6,%7},{%8,%9},{%0,%1,%2,%3};"
                 : "+f"(d.x), "+f"(d.y), "+f"(d.z), "+f"(d.w)
                 : "r"(a[0]), "r"(a[1]), "r"(a[2]), "r"(a[3]), "r"(b0), "r"(b1));
}
__device__ __forceinline__ void mma_f16(float4& d, const uint32_t* a, uint32_t b0, uint32_t b1) {
    asm volatile("mma.sync.aligned.m16n8k16.row.col.f32.f16.f16.f32 "
                 "{%0,%1,%2,%3},{%4,%5,%6,%7},{%8,%9},{%0,%1,%2,%3};"
                 : "+f"(d.x), "+f"(d.y), "+f"(d.z), "+f"(d.w)
                 : "r"(a[0]), "r"(a[1]), "r"(a[2]), "r"(a[3]), "r"(b0), "r"(b1));
}

// ------------------------------------------------------------------ preproc
__global__ void norm_src_kernel(const float* __restrict__ src_desc) {
    int gid = blockIdx.x * blockDim.x + threadIdx.x;   // 4096
    int b = gid >> 10, n = gid & 1023;
    const float* p = src_desc + (size_t)b * 64 * NN + n;
    float xs[64]; float sum = 0.f;
#pragma unroll
    for (int c = 0; c < 64; c++) { xs[c] = p[c * NN]; sum += xs[c]; }
    float mean = sum * (1.f / 64.f), var = 0.f;
#pragma unroll
    for (int c = 0; c < 64; c++) { float d = xs[c] - mean; var += d * d; }
    float inv = rsqrtf(var * (1.f / 63.f));
#pragma unroll
    for (int c = 0; c < 64; c++) {
        float q = (xs[c] - mean) * inv;
        __nv_bfloat16 h = __float2bfloat16(q);
        g_Qh[(size_t)gid * 64 + c] = h;
        g_Ql[(size_t)gid * 64 + c] = __float2bfloat16(q - __bfloat162float(h));
    }
}

__global__ void norm_tgt_kernel(const float* __restrict__ tgt_desc,
                                const float* __restrict__ tgt_coords,
                                const float* __restrict__ tgt_w) {
    __shared__ uint32_t stg[8][32][33];
    int w = threadIdx.x >> 5, lane = threadIdx.x & 31;
    int gbase = blockIdx.x * 256 + w * 32;
    int gid = gbase + lane;                            // 0..262143
    int b = gid >> 16, m = gid & 65535;
    const float* p = tgt_desc + (size_t)b * 64 * MM + m;
    float xs[64]; float sum = 0.f;
#pragma unroll
    for (int c = 0; c < 64; c++) { xs[c] = p[(size_t)c * MM]; sum += xs[c]; }
    float mean = sum * (1.f / 64.f), var = 0.f;
#pragma unroll
    for (int c = 0; c < 64; c++) { float d = xs[c] - mean; var += d * d; }
    float inv = rsqrtf(var * (1.f / 63.f));
    // V^T channel-major (coalesced across lanes)
#pragma unroll
    for (int c = 0; c < 64; c++)
        g_Vt[(((size_t)(b * 72 + c)) << 16) + m] = __float2half(xs[c]);
    g_Vt[(((size_t)(b * 72 + 64)) << 16) + m] = __float2half(tgt_coords[(size_t)(b * 3 + 0) * MM + m]);
    g_Vt[(((size_t)(b * 72 + 65)) << 16) + m] = __float2half(tgt_coords[(size_t)(b * 3 + 1) * MM + m]);
    g_Vt[(((size_t)(b * 72 + 66)) << 16) + m] = __float2half(tgt_coords[(size_t)(b * 3 + 2) * MM + m]);
    g_Vt[(((size_t)(b * 72 + 67)) << 16) + m] = __float2half(tgt_w[(size_t)b * MM + m]);
    g_Vt[(((size_t)(b * 72 + 68)) << 16) + m] = __float2half(1.0f);
    // Kh staged transpose (coalesced row writes)
#pragma unroll
    for (int j = 0; j < 32; j++) {
        float k0 = (xs[2 * j] - mean) * inv, k1 = (xs[2 * j + 1] - mean) * inv;
        __nv_bfloat162 t; t.x = __float2bfloat16(k0); t.y = __float2bfloat16(k1);
        stg[w][lane][j] = *(uint32_t*)&t;
    }
    __syncwarp();
    {
        uint32_t* dst = (uint32_t*)g_Kh + (size_t)gbase * 32;
#pragma unroll
        for (int r = 0; r < 32; r++) dst[(size_t)r * 32 + lane] = stg[w][r][lane];
    }
    __syncwarp();
#pragma unroll
    for (int j = 0; j < 32; j++) {
        float k0 = (xs[2 * j] - mean) * inv, k1 = (xs[2 * j + 1] - mean) * inv;
        __nv_bfloat16 h0 = __float2bfloat16(k0), h1 = __float2bfloat16(k1);
        __nv_bfloat162 t; t.x = __float2bfloat16(k0 - __bfloat162float(h0));
        t.y = __float2bfloat16(k1 - __bfloat162float(h1));
        stg[w][lane][j] = *(uint32_t*)&t;
    }
    __syncwarp();
    {
        uint32_t* dst = (uint32_t*)g_Kl + (size_t)gbase * 32;
#pragma unroll
        for (int r = 0; r < 32; r++) dst[(size_t)r * 32 + lane] = stg[w][r][lane];
    }
}

// ------------------------------------------------------------------ attention (warp MMA)
// smem layout (elements padded to 72 per row = 144B; bank-permutation conflict-free)
#define QROW 72
#define SM_QH 0
#define SM_QL (SM_QH + 128*144)
#define SM_K0 (SM_QL + 128*144)           // buf0: Kh | Kl | VT
#define KH_OFF 0
#define KL_OFF (64*144)
#define VT_OFF (128*144)
#define BUFSZ (128*144 + 72*144)          // 28800 B
#define SM_TOTAL (SM_K0 + 2*BUFSZ)        // 94464 B

__device__ __forceinline__ void load_chunk(char* buf, int b, int kpos, int tid) {
    const __nv_bfloat16* KH = g_Kh + (((size_t)b << 16) + kpos) * 64;
    const __nv_bfloat16* KL = g_Kl + (((size_t)b << 16) + kpos) * 64;
#pragma unroll
    for (int it = 0; it < 2; it++) {
        int i = tid + it * 256;           // 512 items: 64 rows x 8
        int row = i >> 3, j = i & 7;
        cpa16(buf + KH_OFF + row * 144 + j * 16, KH + row * 64 + j * 8);
        cpa16(buf + KL_OFF + row * 144 + j * 16, KL + row * 64 + j * 8);
    }
    for (int i = tid; i < 576; i += 256) { // 72 rows x 8
        int ch = i >> 3, j = i & 7;
        cpa16(buf + VT_OFF + ch * 144 + j * 16,
              g_Vt + (((size_t)(b * 72 + ch)) << 16) + kpos + j * 8);
    }
}

__global__ __launch_bounds__(256, 1) void attn_kernel() {
    extern __shared__ char smem[];
    const int tid = threadIdx.x;
    const int warp = tid >> 5, lane = tid & 31;
    const int q4 = lane >> 2, t = lane & 3;
    const int ks = blockIdx.x, qt = blockIdx.y, b = blockIdx.z;
    const int kbase = ks * (MM / KSPLIT);

    // ---- Q tile to smem (plain stores) ----
    {
        const __nv_bfloat16* QH = g_Qh + ((size_t)(b * 1024 + qt * 128)) * 64;
        const __nv_bfloat16* QL = g_Ql + ((size_t)(b * 1024 + qt * 128)) * 64;
        for (int i = tid; i < 1024; i += 256) {
            int row = i >> 3, j = i & 7;
            *(float4*)(smem + SM_QH + row * 144 + j * 16) = *(const float4*)(QH + row * 64 + j * 8);
            *(float4*)(smem + SM_QL + row * 144 + j * 16) = *(const float4*)(QL + row * 64 + j * 8);
        }
    }
    load_chunk(smem + SM_K0, b, kbase, tid);
    CPA_COMMIT();
    __syncthreads();

    // ---- Q fragments (held in registers for whole kernel) ----
    uint32_t qh[4][4], ql[4][4];
    {
        const int g = 16 * warp + q4;
        const char* QHs = smem + SM_QH;
        const char* QLs = smem + SM_QL;
#pragma unroll
        for (int kk = 0; kk < 4; kk++) {
            int c0 = kk * 16 + t * 2;
            qh[kk][0] = *(const uint32_t*)(QHs + g * 144 + c0 * 2);
            qh[kk][1] = *(const uint32_t*)(QHs + (g + 8) * 144 + c0 * 2);
            qh[kk][2] = *(const uint32_t*)(QHs + g * 144 + (c0 + 8) * 2);
            qh[kk][3] = *(const uint32_t*)(QHs + (g + 8) * 144 + (c0 + 8) * 2);
            ql[kk][0] = *(const uint32_t*)(QLs + g * 144 + c0 * 2);
            ql[kk][1] = *(const uint32_t*)(QLs + (g + 8) * 144 + c0 * 2);
            ql[kk][2] = *(const uint32_t*)(QLs + g * 144 + (c0 + 8) * 2);
            ql[kk][3] = *(const uint32_t*)(QLs + (g + 8) * 144 + (c0 + 8) * 2);
        }
    }

    float4 O[9];
#pragma unroll
    for (int nt = 0; nt < 9; nt++) O[nt] = make_float4(0.f, 0.f, 0.f, 0.f);
    float m_lo = -CUDART_INF_F, m_hi = -CUDART_INF_F;

    for (int i = 0; i < NCHUNK; i++) {
        char* cur = smem + SM_K0 + (i & 1) * BUFSZ;
        if (i + 1 < NCHUNK) {
            load_chunk(smem + SM_K0 + ((i + 1) & 1) * BUFSZ, b, kbase + (i + 1) * TK, tid);
            CPA_COMMIT();
            CPA_WAIT(1);
        } else {
            CPA_WAIT(0);
        }
        __syncthreads();

        // ---- S = Q K^T (split bf16: hh + hl + lh) ----
        float4 s[8];
        const int rb = (q4) * 144 + t * 4;   // within 8-row n-tile
#pragma unroll
        for (int nt = 0; nt < 8; nt++) {
            s[nt] = make_float4(0.f, 0.f, 0.f, 0.f);
            const char* kh = cur + KH_OFF + nt * 8 * 144 + rb;
            const char* kl = cur + KL_OFF + nt * 8 * 144 + rb;
#pragma unroll
            for (int kk = 0; kk < 4; kk++) {
                uint32_t bh0 = *(const uint32_t*)(kh + kk * 32);
                uint32_t bh1 = *(const uint32_t*)(kh + kk * 32 + 16);
                uint32_t bl0 = *(const uint32_t*)(kl + kk * 32);
                uint32_t bl1 = *(const uint32_t*)(kl + kk * 32 + 16);
                mma_bf16(s[nt], qh[kk], bh0, bh1);
                mma_bf16(s[nt], qh[kk], bl0, bl1);
                mma_bf16(s[nt], ql[kk], bh0, bh1);
            }
        }

        // ---- online softmax (rows warp-private; quad reduce) ----
        float mx_lo = -CUDART_INF_F, mx_hi = -CUDART_INF_F;
#pragma unroll
        for (int nt = 0; nt < 8; nt++) {
            mx_lo = fmaxf(mx_lo, fmaxf(s[nt].x, s[nt].y));
            mx_hi = fmaxf(mx_hi, fmaxf(s[nt].z, s[nt].w));
        }
        mx_lo = fmaxf(mx_lo, __shfl_xor_sync(0xffffffffu, mx_lo, 1));
        mx_lo = fmaxf(mx_lo, __shfl_xor_sync(0xffffffffu, mx_lo, 2));
        mx_hi = fmaxf(mx_hi, __shfl_xor_sync(0xffffffffu, mx_hi, 1));
        mx_hi = fmaxf(mx_hi, __shfl_xor_sync(0xffffffffu, mx_hi, 2));
        float mn_lo = fmaxf(m_lo, mx_lo), mn_hi = fmaxf(m_hi, mx_hi);
        float corr_lo = ex2(K2 * (m_lo - mn_lo));
        float corr_hi = ex2(K2 * (m_hi - mn_hi));
        m_lo = mn_lo; m_hi = mn_hi;

        // P fragments (fp16), directly as A-fragments of the PV mma
        uint32_t pa[4][4];
#pragma unroll
        for (int kk = 0; kk < 4; kk++) {
            float4 sA = s[2 * kk], sB = s[2 * kk + 1];
            pa[kk][0] = pkh2(ex2(K2 * (sA.y - m_lo)), ex2(K2 * (sA.x - m_lo)));
            pa[kk][1] = pkh2(ex2(K2 * (sA.w - m_hi)), ex2(K2 * (sA.z - m_hi)));
            pa[kk][2] = pkh2(ex2(K2 * (sB.y - m_lo)), ex2(K2 * (sB.x - m_lo)));
            pa[kk][3] = pkh2(ex2(K2 * (sB.w - m_hi)), ex2(K2 * (sB.z - m_hi)));
        }

        // ---- rescale O, then O += P V ----
#pragma unroll
        for (int nt = 0; nt < 9; nt++) {
            O[nt].x *= corr_lo; O[nt].y *= corr_lo;
            O[nt].z *= corr_hi; O[nt].w *= corr_hi;
        }
#pragma unroll
        for (int nt = 0; nt < 9; nt++) {
            const char* vrow = cur + VT_OFF + nt * 8 * 144 + rb;
#pragma unroll
            for (int kk = 0; kk < 4; kk++) {
                uint32_t b0 = *(const uint32_t*)(vrow + kk * 32);
                uint32_t b1 = *(const uint32_t*)(vrow + kk * 32 + 16);
                mma_f16(O[nt], pa[kk], b0, b1);
            }
        }
        __syncthreads();
    }

    // ---- write partials: [blk][ch][r], l at ch 68 ----
    const int blk = (b * 8 + qt) * KSPLIT + ks;
    float* P = g_part + (size_t)blk * 69 * 128;
    const int r0 = 16 * warp + q4, r1 = r0 + 8;
#pragma unroll
    for (int nt = 0; nt < 9; nt++) {
        int ch = 8 * nt + 2 * t;
        if (ch <= 68) { P[ch * 128 + r0] = O[nt].x; P[ch * 128 + r1] = O[nt].z; }
        if (ch + 1 <= 68) { P[(ch + 1) * 128 + r0] = O[nt].y; P[(ch + 1) * 128 + r1] = O[nt].w; }
    }
    if (t == 0) { g_pm[blk * 128 + r0] = m_lo; g_pm[blk * 128 + r1] = m_hi; }
}

// ------------------------------------------------------------------ combine + epilogue
__global__ void combine_kernel(float* __restrict__ out) {
    int gq = blockIdx.x * blockDim.x + threadIdx.x;   // 4096
    int b = gq >> 10, n = gq & 1023;
    int qt = n >> 7, r = gq & 127;
    int blk0 = (b * 8 + qt) * KSPLIT;

    float Mx = -CUDART_INF_F;
#pragma unroll
    for (int s = 0; s < KSPLIT; s++) Mx = fmaxf(Mx, g_pm[(blk0 + s) * 128 + r]);

    float val[69];
#pragma unroll
    for (int ch = 0; ch < 69; ch++) val[ch] = 0.f;
    for (int s = 0; s < KSPLIT; s++) {
        float w = __expf(SCALE * (g_pm[(blk0 + s) * 128 + r] - Mx));
        const float* Op = g_part + (size_t)(blk0 + s) * 69 * 128;
#pragma unroll
        for (int ch = 0; ch < 69; ch++) val[ch] += Op[ch * 128 + r] * w;
    }
    float invL = 1.f / val[68];
#pragma unroll
    for (int ch = 0; ch < 68; ch++) val[ch] *= invL;

    float x = val[64], y = val[65], z = val[66], wgt = val[67];

    float sum = 0.f;
#pragma unroll
    for (int c = 0; c < 64; c++) sum += val[c];
    float mean = sum * (1.f / 64.f), var = 0.f;
#pragma unroll
    for (int c = 0; c < 64; c++) { float d = val[c] - mean; var += d * d; }
    float inv = rsqrtf(var * (1.f / 63.f));

    out[(b * 3 + 0) * 1024 + n] = x;
    out[(b * 3 + 1) * 1024 + n] = y;
    out[(b * 3 + 2) * 1024 + n] = z;
    out[12288 + b * 1024 + n] = wgt;
#pragma unroll
    for (int c = 0; c < 64; c++)
        out[16384 + (b * 64 + c) * 1024 + n] = (val[c] - mean) * inv;

    float rr = sqrtf(x * x + y * y + z * z);
    float az = atan2f(y, x);
    float el = asinf(z / (rr + 1e-12f));
    float u = 0.5f * (1.0f - az * (1.0f / CUDART_PI_F)) * 1024.0f;
    float v = (1.0f - (el + 0.4363323129985824f) * (1.0f / 0.4886921905584123f)) * 64.0f;
    u = fminf(fmaxf(u, 0.f), 1023.f);
    v = fminf(fmaxf(v, 0.f), 63.f);
    out[278528 + gq * 2 + 0] = u;
    out[278528 + gq * 2 + 1] = v;
    out[286720 + b * 1024 + n] = 1.0f;
}

// ------------------------------------------------------------------
extern "C" void kernel_launch(void* const* d_in, const int* in_sizes, int n_in,
                              void* d_out, int out_size) {
    const float* tgt_coords = (const float*)d_in[1];
    const float* tgt_w      = (const float*)d_in[2];
    const float* src_desc   = (const float*)d_in[3];
    const float* tgt_desc   = (const float*)d_in[4];
    float* out = (float*)d_out;

    cudaFuncSetAttribute(attn_kernel, cudaFuncAttributeMaxDynamicSharedMemorySize, SM_TOTAL);

    norm_src_kernel<<<16, 256>>>(src_desc);
    norm_tgt_kernel<<<1024, 256>>>(tgt_desc, tgt_coords, tgt_w);
    attn_kernel<<<dim3(KSPLIT, 8, BB), 256, SM_TOTAL>>>();
    combine_kernel<<<16, 256>>>(out);
}

// round 9
// speedup vs baseline: 10.1213x; 1.0306x over previous
#include <cuda_runtime.h>
#include <cuda_fp16.h>
#include <cuda_bf16.h>
#include <math_constants.h>
#include <cstdint>

#define BB 4
#define NN 1024
#define MM 65536
#define SCALE 1.5625f                 // 1/(64*0.01)
#define K2 2.2542110013900995f        // SCALE * log2(e)
#define KSPLIT 8
#define TK 64
#define NCHUNK (MM/KSPLIT/TK)         // 128
#define NBLK (BB*8*KSPLIT)            // 256

// ------------------------------------------------------------------ scratch
__device__ __nv_bfloat16 g_Qh[BB*NN*64];            // [b*1024+n][64]
__device__ __nv_bfloat16 g_Ql[BB*NN*64];
__device__ __nv_bfloat16 g_Kh[(size_t)BB*MM*64];    // [(b<<16)+m][64]
__device__ __nv_bfloat16 g_Kl[(size_t)BB*MM*64];
__device__ __half        g_Vt[(size_t)BB*72*MM];    // [b*72+ch][m]; ch68=ones, 69-71 zero (.bss)
__device__ float g_part[(size_t)NBLK*69*128];       // [blk][ch][r]
__device__ float g_pm[NBLK*128];

// ------------------------------------------------------------------ helpers
__device__ __forceinline__ uint32_t smem_u32(const void* p) {
    uint32_t a;
    asm("{ .reg .u64 t; cvta.to.shared.u64 t, %1; cvt.u32.u64 %0, t; }" : "=r"(a) : "l"(p));
    return a;
}
__device__ __forceinline__ void cpa16(void* dst, const void* src) {
    uint32_t d = smem_u32(dst);
    asm volatile("cp.async.cg.shared.global [%0], [%1], 16;" :: "r"(d), "l"(src) : "memory");
}
#define CPA_COMMIT() asm volatile("cp.async.commit_group;" ::: "memory")
#define CPA_WAIT(n)  asm volatile("cp.async.wait_group %0;" :: "n"(n) : "memory")

__device__ __forceinline__ float ex2(float x) {
    float y; asm("ex2.approx.ftz.f32 %0, %1;" : "=f"(y) : "f"(x)); return y;
}
__device__ __forceinline__ uint32_t pkh2(float hi, float lo) {
    uint32_t d; asm("cvt.rn.f16x2.f32 %0, %1, %2;" : "=r"(d) : "f"(hi), "f"(lo)); return d;
}
__device__ __forceinline__ void mma_bf16(float4& d, const uint32_t* a, uint32_t b0, uint32_t b1) {
    asm volatile("mma.sync.aligned.m16n8k16.row.col.f32.bf16.bf16.f32 "
                 "{%0,%1,%2,%3},{%4,%5,%6,%7},{%8,%9},{%0,%1,%2,%3};"
                 : "+f"(d.x), "+f"(d.y), "+f"(d.z), "+f"(d.w)
                 : "r"(a[0]), "r"(a[1]), "r"(a[2]), "r"(a[3]), "r"(b0), "r"(b1));
}
__device__ __forceinline__ void mma_f16(float4& d, const uint32_t* a, uint32_t b0, uint32_t b1) {
    asm volatile("mma.sync.aligned.m16n8k16.row.col.f32.f16.f16.f32 "
                 "{%0,%1,%2,%3},{%4,%5,%6,%7},{%8,%9},{%0,%1,%2,%3};"
                 : "+f"(d.x), "+f"(d.y), "+f"(d.z), "+f"(d.w)
                 : "r"(a[0]), "r"(a[1]), "r"(a[2]), "r"(a[3]), "r"(b0), "r"(b1));
}

// ------------------------------------------------------------------ preproc
__global__ void norm_src_kernel(const float* __restrict__ src_desc) {
    int gid = blockIdx.x * blockDim.x + threadIdx.x;   // 4096
    int b = gid >> 10, n = gid & 1023;
    const float* p = src_desc + (size_t)b * 64 * NN + n;
    float xs[64]; float sum = 0.f;
#pragma unroll
    for (int c = 0; c < 64; c++) { xs[c] = p[c * NN]; sum += xs[c]; }
    float mean = sum * (1.f / 64.f), var = 0.f;
#pragma unroll
    for (int c = 0; c < 64; c++) { float d = xs[c] - mean; var += d * d; }
    float inv = rsqrtf(var * (1.f / 63.f));
#pragma unroll
    for (int c = 0; c < 64; c++) {
        float q = (xs[c] - mean) * inv;
        __nv_bfloat16 h = __float2bfloat16(q);
        g_Qh[(size_t)gid * 64 + c] = h;
        g_Ql[(size_t)gid * 64 + c] = __float2bfloat16(q - __bfloat162float(h));
    }
}

__global__ void norm_tgt_kernel(const float* __restrict__ tgt_desc,
                                const float* __restrict__ tgt_coords,
                                const float* __restrict__ tgt_w) {
    __shared__ uint32_t stg[8][32][33];
    int w = threadIdx.x >> 5, lane = threadIdx.x & 31;
    int gbase = blockIdx.x * 256 + w * 32;
    int gid = gbase + lane;                            // 0..262143
    int b = gid >> 16, m = gid & 65535;
    const float* p = tgt_desc + (size_t)b * 64 * MM + m;
    float xs[64]; float sum = 0.f;
#pragma unroll
    for (int c = 0; c < 64; c++) { xs[c] = p[(size_t)c * MM]; sum += xs[c]; }
    float mean = sum * (1.f / 64.f), var = 0.f;
#pragma unroll
    for (int c = 0; c < 64; c++) { float d = xs[c] - mean; var += d * d; }
    float inv = rsqrtf(var * (1.f / 63.f));
    // V^T channel-major (coalesced across lanes)
#pragma unroll
    for (int c = 0; c < 64; c++)
        g_Vt[(((size_t)(b * 72 + c)) << 16) + m] = __float2half(xs[c]);
    g_Vt[(((size_t)(b * 72 + 64)) << 16) + m] = __float2half(tgt_coords[(size_t)(b * 3 + 0) * MM + m]);
    g_Vt[(((size_t)(b * 72 + 65)) << 16) + m] = __float2half(tgt_coords[(size_t)(b * 3 + 1) * MM + m]);
    g_Vt[(((size_t)(b * 72 + 66)) << 16) + m] = __float2half(tgt_coords[(size_t)(b * 3 + 2) * MM + m]);
    g_Vt[(((size_t)(b * 72 + 67)) << 16) + m] = __float2half(tgt_w[(size_t)b * MM + m]);
    g_Vt[(((size_t)(b * 72 + 68)) << 16) + m] = __float2half(1.0f);
    // Kh staged transpose (coalesced row writes)
#pragma unroll
    for (int j = 0; j < 32; j++) {
        float k0 = (xs[2 * j] - mean) * inv, k1 = (xs[2 * j + 1] - mean) * inv;
        __nv_bfloat162 t; t.x = __float2bfloat16(k0); t.y = __float2bfloat16(k1);
        stg[w][lane][j] = *(uint32_t*)&t;
    }
    __syncwarp();
    {
        uint32_t* dst = (uint32_t*)g_Kh + (size_t)gbase * 32;
#pragma unroll
        for (int r = 0; r < 32; r++) dst[(size_t)r * 32 + lane] = stg[w][r][lane];
    }
    __syncwarp();
#pragma unroll
    for (int j = 0; j < 32; j++) {
        float k0 = (xs[2 * j] - mean) * inv, k1 = (xs[2 * j + 1] - mean) * inv;
        __nv_bfloat16 h0 = __float2bfloat16(k0), h1 = __float2bfloat16(k1);
        __nv_bfloat162 t; t.x = __float2bfloat16(k0 - __bfloat162float(h0));
        t.y = __float2bfloat16(k1 - __bfloat162float(h1));
        stg[w][lane][j] = *(uint32_t*)&t;
    }
    __syncwarp();
    {
        uint32_t* dst = (uint32_t*)g_Kl + (size_t)gbase * 32;
#pragma unroll
        for (int r = 0; r < 32; r++) dst[(size_t)r * 32 + lane] = stg[w][r][lane];
    }
}

// ------------------------------------------------------------------ attention (warp MMA)
// smem layout (rows padded to 72 elements = 144B; bank-permutation conflict-free)
#define SM_QH 0
#define SM_QL (SM_QH + 128*144)
#define SM_K0 (SM_QL + 128*144)           // buf0: Kh | Kl | VT
#define KH_OFF 0
#define KL_OFF (64*144)
#define VT_OFF (128*144)
#define BUFSZ (128*144 + 72*144)          // 28800 B
#define SM_TOTAL (SM_K0 + 2*BUFSZ)        // 94464 B

__device__ __forceinline__ void load_chunk(char* buf, int b, int kpos, int tid) {
    const __nv_bfloat16* KH = g_Kh + (((size_t)b << 16) + kpos) * 64;
    const __nv_bfloat16* KL = g_Kl + (((size_t)b << 16) + kpos) * 64;
#pragma unroll
    for (int it = 0; it < 2; it++) {
        int i = tid + it * 256;           // 512 items: 64 rows x 8
        int row = i >> 3, j = i & 7;
        cpa16(buf + KH_OFF + row * 144 + j * 16, KH + row * 64 + j * 8);
        cpa16(buf + KL_OFF + row * 144 + j * 16, KL + row * 64 + j * 8);
    }
    for (int i = tid; i < 576; i += 256) { // 72 rows x 8
        int ch = i >> 3, j = i & 7;
        cpa16(buf + VT_OFF + ch * 144 + j * 16,
              g_Vt + (((size_t)(b * 72 + ch)) << 16) + kpos + j * 8);
    }
}

__global__ __launch_bounds__(256, 2) void attn_kernel() {
    extern __shared__ char smem[];
    const int tid = threadIdx.x;
    const int warp = tid >> 5, lane = tid & 31;
    const int q4 = lane >> 2, t = lane & 3;
    const int ks = blockIdx.x, qt = blockIdx.y, b = blockIdx.z;
    const int kbase = ks * (MM / KSPLIT);

    // ---- Q tile to smem ----
    {
        const __nv_bfloat16* QH = g_Qh + ((size_t)(b * 1024 + qt * 128)) * 64;
        const __nv_bfloat16* QL = g_Ql + ((size_t)(b * 1024 + qt * 128)) * 64;
        for (int i = tid; i < 1024; i += 256) {
            int row = i >> 3, j = i & 7;
            *(float4*)(smem + SM_QH + row * 144 + j * 16) = *(const float4*)(QH + row * 64 + j * 8);
            *(float4*)(smem + SM_QL + row * 144 + j * 16) = *(const float4*)(QL + row * 64 + j * 8);
        }
    }
    load_chunk(smem + SM_K0, b, kbase, tid);
    CPA_COMMIT();
    __syncthreads();

    // ---- Q fragments (persistent in registers) ----
    uint32_t qh[4][4], ql[4][4];
    {
        const int g = 16 * warp + q4;
        const char* QHs = smem + SM_QH;
        const char* QLs = smem + SM_QL;
#pragma unroll
        for (int kk = 0; kk < 4; kk++) {
            int c0 = kk * 16 + t * 2;
            qh[kk][0] = *(const uint32_t*)(QHs + g * 144 + c0 * 2);
            qh[kk][1] = *(const uint32_t*)(QHs + (g + 8) * 144 + c0 * 2);
            qh[kk][2] = *(const uint32_t*)(QHs + g * 144 + (c0 + 8) * 2);
            qh[kk][3] = *(const uint32_t*)(QHs + (g + 8) * 144 + (c0 + 8) * 2);
            ql[kk][0] = *(const uint32_t*)(QLs + g * 144 + c0 * 2);
            ql[kk][1] = *(const uint32_t*)(QLs + (g + 8) * 144 + c0 * 2);
            ql[kk][2] = *(const uint32_t*)(QLs + g * 144 + (c0 + 8) * 2);
            ql[kk][3] = *(const uint32_t*)(QLs + (g + 8) * 144 + (c0 + 8) * 2);
        }
    }

    float4 O[9];
#pragma unroll
    for (int nt = 0; nt < 9; nt++) O[nt] = make_float4(0.f, 0.f, 0.f, 0.f);
    float m_lo = -CUDART_INF_F, m_hi = -CUDART_INF_F;

    for (int i = 0; i < NCHUNK; i++) {
        char* cur = smem + SM_K0 + (i & 1) * BUFSZ;
        if (i + 1 < NCHUNK) {
            load_chunk(smem + SM_K0 + ((i + 1) & 1) * BUFSZ, b, kbase + (i + 1) * TK, tid);
            CPA_COMMIT();
            CPA_WAIT(1);
        } else {
            CPA_WAIT(0);
        }
        __syncthreads();

        // ---- S = Q K^T (split bf16: hh + hl + lh) ----
        float4 s[8];
        const int rb = q4 * 144 + t * 4;
#pragma unroll
        for (int nt = 0; nt < 8; nt++) {
            s[nt] = make_float4(0.f, 0.f, 0.f, 0.f);
            const char* kh = cur + KH_OFF + nt * 8 * 144 + rb;
            const char* kl = cur + KL_OFF + nt * 8 * 144 + rb;
#pragma unroll
            for (int kk = 0; kk < 4; kk++) {
                uint32_t bh0 = *(const uint32_t*)(kh + kk * 32);
                uint32_t bh1 = *(const uint32_t*)(kh + kk * 32 + 16);
                uint32_t bl0 = *(const uint32_t*)(kl + kk * 32);
                uint32_t bl1 = *(const uint32_t*)(kl + kk * 32 + 16);
                mma_bf16(s[nt], qh[kk], bh0, bh1);
                mma_bf16(s[nt], qh[kk], bl0, bl1);
                mma_bf16(s[nt], ql[kk], bh0, bh1);
            }
        }

        // ---- online softmax (rows warp-private; quad reduce) ----
        float mx_lo = -CUDART_INF_F, mx_hi = -CUDART_INF_F;
#pragma unroll
        for (int nt = 0; nt < 8; nt++) {
            mx_lo = fmaxf(mx_lo, fmaxf(s[nt].x, s[nt].y));
            mx_hi = fmaxf(mx_hi, fmaxf(s[nt].z, s[nt].w));
        }
        mx_lo = fmaxf(mx_lo, __shfl_xor_sync(0xffffffffu, mx_lo, 1));
        mx_lo = fmaxf(mx_lo, __shfl_xor_sync(0xffffffffu, mx_lo, 2));
        mx_hi = fmaxf(mx_hi, __shfl_xor_sync(0xffffffffu, mx_hi, 1));
        mx_hi = fmaxf(mx_hi, __shfl_xor_sync(0xffffffffu, mx_hi, 2));
        float mn_lo = fmaxf(m_lo, mx_lo), mn_hi = fmaxf(m_hi, mx_hi);

        // rescale only when some row max actually moved (rare: peaked softmax)
        bool chg = (mn_lo > m_lo) || (mn_hi > m_hi);
        if (__any_sync(0xffffffffu, chg)) {
            float corr_lo = ex2(K2 * (m_lo - mn_lo));
            float corr_hi = ex2(K2 * (m_hi - mn_hi));
#pragma unroll
            for (int nt = 0; nt < 9; nt++) {
                O[nt].x *= corr_lo; O[nt].y *= corr_lo;
                O[nt].z *= corr_hi; O[nt].w *= corr_hi;
            }
        }
        m_lo = mn_lo; m_hi = mn_hi;

        // P fragments (fp16), directly as A-fragments of the PV mma
        uint32_t pa[4][4];
#pragma unroll
        for (int kk = 0; kk < 4; kk++) {
            float4 sA = s[2 * kk], sB = s[2 * kk + 1];
            pa[kk][0] = pkh2(ex2(K2 * (sA.y - m_lo)), ex2(K2 * (sA.x - m_lo)));
            pa[kk][1] = pkh2(ex2(K2 * (sA.w - m_hi)), ex2(K2 * (sA.z - m_hi)));
            pa[kk][2] = pkh2(ex2(K2 * (sB.y - m_lo)), ex2(K2 * (sB.x - m_lo)));
            pa[kk][3] = pkh2(ex2(K2 * (sB.w - m_hi)), ex2(K2 * (sB.z - m_hi)));
        }

        // ---- O += P V ----
#pragma unroll
        for (int nt = 0; nt < 9; nt++) {
            const char* vrow = cur + VT_OFF + nt * 8 * 144 + rb;
#pragma unroll
            for (int kk = 0; kk < 4; kk++) {
                uint32_t b0 = *(const uint32_t*)(vrow + kk * 32);
                uint32_t b1 = *(const uint32_t*)(vrow + kk * 32 + 16);
                mma_f16(O[nt], pa[kk], b0, b1);
            }
        }
        __syncthreads();
    }

    // ---- write partials: [blk][ch][r], l at ch 68 ----
    const int blk = (b * 8 + qt) * KSPLIT + ks;
    float* P = g_part + (size_t)blk * 69 * 128;
    const int r0 = 16 * warp + q4, r1 = r0 + 8;
#pragma unroll
    for (int nt = 0; nt < 9; nt++) {
        int ch = 8 * nt + 2 * t;
        if (ch <= 68) { P[ch * 128 + r0] = O[nt].x; P[ch * 128 + r1] = O[nt].z; }
        if (ch + 1 <= 68) { P[(ch + 1) * 128 + r0] = O[nt].y; P[(ch + 1) * 128 + r1] = O[nt].w; }
    }
    if (t == 0) { g_pm[blk * 128 + r0] = m_lo; g_pm[blk * 128 + r1] = m_hi; }
}

// ------------------------------------------------------------------ combine + epilogue
__global__ void combine_kernel(float* __restrict__ out) {
    int gq = blockIdx.x * blockDim.x + threadIdx.x;   // 4096
    int b = gq >> 10, n = gq & 1023;
    int qt = n >> 7, r = gq & 127;
    int blk0 = (b * 8 + qt) * KSPLIT;

    float Mx = -CUDART_INF_F;
#pragma unroll
    for (int s = 0; s < KSPLIT; s++) Mx = fmaxf(Mx, g_pm[(blk0 + s) * 128 + r]);

    float val[69];
#pragma unroll
    for (int ch = 0; ch < 69; ch++) val[ch] = 0.f;
    for (int s = 0; s < KSPLIT; s++) {
        float w = __expf(SCALE * (g_pm[(blk0 + s) * 128 + r] - Mx));
        const float* Op = g_part + (size_t)(blk0 + s) * 69 * 128;
#pragma unroll
        for (int ch = 0; ch < 69; ch++) val[ch] += Op[ch * 128 + r] * w;
    }
    float invL = 1.f / val[68];
#pragma unroll
    for (int ch = 0; ch < 68; ch++) val[ch] *= invL;

    float x = val[64], y = val[65], z = val[66], wgt = val[67];

    float sum = 0.f;
#pragma unroll
    for (int c = 0; c < 64; c++) sum += val[c];
    float mean = sum * (1.f / 64.f), var = 0.f;
#pragma unroll
    for (int c = 0; c < 64; c++) { float d = val[c] - mean; var += d * d; }
    float inv = rsqrtf(var * (1.f / 63.f));

    out[(b * 3 + 0) * 1024 + n] = x;
    out[(b * 3 + 1) * 1024 + n] = y;
    out[(b * 3 + 2) * 1024 + n] = z;
    out[12288 + b * 1024 + n] = wgt;
#pragma unroll
    for (int c = 0; c < 64; c++)
        out[16384 + (b * 64 + c) * 1024 + n] = (val[c] - mean) * inv;

    float rr = sqrtf(x * x + y * y + z * z);
    float az = atan2f(y, x);
    float el = asinf(z / (rr + 1e-12f));
    float u = 0.5f * (1.0f - az * (1.0f / CUDART_PI_F)) * 1024.0f;
    float v = (1.0f - (el + 0.4363323129985824f) * (1.0f / 0.4886921905584123f)) * 64.0f;
    u = fminf(fmaxf(u, 0.f), 1023.f);
    v = fminf(fmaxf(v, 0.f), 63.f);
    out[278528 + gq * 2 + 0] = u;
    out[278528 + gq * 2 + 1] = v;
    out[286720 + b * 1024 + n] = 1.0f;
}

// ------------------------------------------------------------------
extern "C" void kernel_launch(void* const* d_in, const int* in_sizes, int n_in,
                              void* d_out, int out_size) {
    const float* tgt_coords = (const float*)d_in[1];
    const float* tgt_w      = (const float*)d_in[2];
    const float* src_desc   = (const float*)d_in[3];
    const float* tgt_desc   = (const float*)d_in[4];
    float* out = (float*)d_out;

    cudaFuncSetAttribute(attn_kernel, cudaFuncAttributeMaxDynamicSharedMemorySize, SM_TOTAL);

    norm_src_kernel<<<16, 256>>>(src_desc);
    norm_tgt_kernel<<<1024, 256>>>(tgt_desc, tgt_coords, tgt_w);
    attn_kernel<<<dim3(KSPLIT, 8, BB), 256, SM_TOTAL>>>();
    combine_kernel<<<128, 32>>>(out);
}